// round 9
// baseline (speedup 1.0000x reference)
#include <cuda_runtime.h>

// LSTMNet: 3-layer LSTM (H=6, input=1), B=8192, T=512, FC head on final h2.
// Round 9: R8 (f32x2 packed ACROSS ELEMENTS, 2 elems/lane, 10/warp) with NO
// weight hoisting: all weight matrices stream from smem (conflict-free),
// keeping regs ~160 (R8 hit the 255 ceiling and spilled; R4/R6 same lesson).
// 820 warps -> 137 blocks x 6 warps, single wave.

#define HD 6
#define TT 512
#define PK 292     // floats per lane-k slice; 1168B stride == 16 mod 128 -> conflict-free
#define WPB 6
#define TPB (WPB * 32)
#define EPW 10     // elements per warp
__device__ float g_packk[6 * PK];

// per-k slice layout (floats; ALL values prescaled: sigmoid rows * -log2e,
// tanh row * -2log2e; every weight/bias duplicated as (w,w) pairs):
//   0: b0 dup (8)        8: wx0 dup (8)       16+8j: Whh0 col j dup (j=0..5)
//  64: b1 dup (8)       72+8j: Wih1 col j    120+8j: Whh1 col j
// 168: b2 dup (8)      176+8j: Wih2 col j    224+8j: Whh2 col j
// 288: fc_w[k]  289: fc_b

__global__ void prep_kernel(
    const float* __restrict__ Wih0, const float* __restrict__ Whh0,
    const float* __restrict__ bih0, const float* __restrict__ bhh0,
    const float* __restrict__ Wih1, const float* __restrict__ Whh1,
    const float* __restrict__ bih1, const float* __restrict__ bhh1,
    const float* __restrict__ Wih2, const float* __restrict__ Whh2,
    const float* __restrict__ bih2, const float* __restrict__ bhh2,
    const float* __restrict__ fcw, const float* __restrict__ fcb)
{
    int tid = threadIdx.x;
    if (tid < 24) {
        int k = tid / 4, g = tid % 4;
        float s = (g == 2) ? -2.88539008177793f : -1.44269504088896f;
        int row = g * HD + k;             // PyTorch gate order i,f,g,o
        float* p = g_packk + k * PK;
        float v;
        v = (bih0[row] + bhh0[row]) * s;  p[0 + 2*g] = v;   p[1 + 2*g] = v;
        v = Wih0[row] * s;                p[8 + 2*g] = v;   p[9 + 2*g] = v;
        v = (bih1[row] + bhh1[row]) * s;  p[64 + 2*g] = v;  p[65 + 2*g] = v;
        v = (bih2[row] + bhh2[row]) * s;  p[168 + 2*g] = v; p[169 + 2*g] = v;
        for (int j = 0; j < HD; j++) {
            v = Whh0[row * HD + j] * s;  p[16  + 8*j + 2*g] = v; p[17  + 8*j + 2*g] = v;
            v = Wih1[row * HD + j] * s;  p[72  + 8*j + 2*g] = v; p[73  + 8*j + 2*g] = v;
            v = Whh1[row * HD + j] * s;  p[120 + 8*j + 2*g] = v; p[121 + 8*j + 2*g] = v;
            v = Wih2[row * HD + j] * s;  p[176 + 8*j + 2*g] = v; p[177 + 8*j + 2*g] = v;
            v = Whh2[row * HD + j] * s;  p[224 + 8*j + 2*g] = v; p[225 + 8*j + 2*g] = v;
        }
    }
    if (tid < 6) {
        g_packk[tid * PK + 288] = fcw[tid];
        g_packk[tid * PK + 289] = fcb[0];
    }
}

typedef unsigned long long ull;

// ---- f32x2 + fast-math primitives ----
__device__ __forceinline__ void fma2(ull& d, ull a, ull b, ull c) {
    asm("fma.rn.f32x2 %0, %1, %2, %3;" : "=l"(d) : "l"(a), "l"(b), "l"(c));
}
__device__ __forceinline__ void mul2(ull& d, ull a, ull b) {
    asm("mul.rn.f32x2 %0, %1, %2;" : "=l"(d) : "l"(a), "l"(b));
}
__device__ __forceinline__ void add2(ull& d, ull a, ull b) {
    asm("add.rn.f32x2 %0, %1, %2;" : "=l"(d) : "l"(a), "l"(b));
}
__device__ __forceinline__ ull pack2(float x, float y) {
    ull d; asm("mov.b64 %0, {%1, %2};" : "=l"(d) : "f"(x), "f"(y)); return d;
}
__device__ __forceinline__ void unpack2(float& x, float& y, ull v) {
    asm("mov.b64 {%0, %1}, %2;" : "=f"(x), "=f"(y) : "l"(v));
}
__device__ __forceinline__ float ex2_ap(float x) {
    float y; asm("ex2.approx.f32 %0, %1;" : "=f"(y) : "f"(x)); return y;
}
__device__ __forceinline__ float rcp_ap(float x) {
    float y; asm("rcp.approx.f32 %0, %1;" : "=f"(y) : "f"(x)); return y;
}

// one element's cell from prescaled gate pre-activations (paired-rcp trick)
__device__ __forceinline__ void cell_s(float ai, float af, float ag, float ao,
                                       float& c, float& h)
{
    float ei = ex2_ap(ai), ef = ex2_ap(af), eg = ex2_ap(ag), eo = ex2_ap(ao);
    float a1 = 1.f + ei, a2 = 1.f + ef, a3 = 1.f + eg, a4 = 1.f + eo;
    float r1 = rcp_ap(a1 * a2);
    float r2 = rcp_ap(a3 * a4);
    float si = r1 * a2;
    float sf = r1 * a1;
    float so = r2 * a3;
    float tg = fmaf(r2 * a4, 2.f, -1.f);
    c = fmaf(sf, c, si * tg);
    float ec = ex2_ap(c * -2.88539008177793f);
    float th = fmaf(rcp_ap(1.f + ec), 2.f, -1.f);
    h = so * th;
}

// unpack 4 gate-pairs (packed across elements), run both cells, broadcast+pack
#define CELL_BCAST(AI, AF, AG, AO, CA, CB, HA, HB, HP)                 \
    {   float ia_, ib_, fa_, fb_, ga_, gb_, oa_, ob_;                  \
        unpack2(ia_, ib_, AI); unpack2(fa_, fb_, AF);                  \
        unpack2(ga_, gb_, AG); unpack2(oa_, ob_, AO);                  \
        cell_s(ia_, fa_, ga_, oa_, CA, HA);                            \
        cell_s(ib_, fb_, gb_, ob_, CB, HB);                            \
        _Pragma("unroll")                                              \
        for (int j = 0; j < HD; j++) {                                 \
            float va_ = __shfl_sync(0xffffffffu, HA, sb + j);          \
            float vb_ = __shfl_sync(0xffffffffu, HB, sb + j);          \
            (HP)[j] = pack2(va_, vb_);                                 \
        }                                                              \
    }

// full-layer macro: gates = bias + Win @ VIN + Wrec @ VREC (2 chains x 4 gates)
// W*: ulonglong2 arrays; col j -> [2j] = (i,f), [2j+1] = (g,o)
#define LAYER(WIN, VIN, WREC, VREC, BI, BF, BG, BO, CA, CB, HA, HB, HP) \
    {   ull ai, af, ag, ao, qi, qf, qg, qo;                            \
        {   ulonglong2 wa = (WIN)[0], wb = (WIN)[1];                   \
            fma2(ai, wa.x, (VIN)[0], BI);                              \
            fma2(af, wa.y, (VIN)[0], BF);                              \
            fma2(ag, wb.x, (VIN)[0], BG);                              \
            fma2(ao, wb.y, (VIN)[0], BO); }                            \
        _Pragma("unroll")                                              \
        for (int j = 1; j < HD; j++) {                                 \
            ulonglong2 wa = (WIN)[2*j], wb = (WIN)[2*j+1];             \
            fma2(ai, wa.x, (VIN)[j], ai);                              \
            fma2(af, wa.y, (VIN)[j], af);                              \
            fma2(ag, wb.x, (VIN)[j], ag);                              \
            fma2(ao, wb.y, (VIN)[j], ao);                              \
        }                                                              \
        {   ulonglong2 wa = (WREC)[0], wb = (WREC)[1];                 \
            mul2(qi, wa.x, (VREC)[0]);                                 \
            mul2(qf, wa.y, (VREC)[0]);                                 \
            mul2(qg, wb.x, (VREC)[0]);                                 \
            mul2(qo, wb.y, (VREC)[0]); }                               \
        _Pragma("unroll")                                              \
        for (int j = 1; j < HD; j++) {                                 \
            ulonglong2 wa = (WREC)[2*j], wb = (WREC)[2*j+1];           \
            fma2(qi, wa.x, (VREC)[j], qi);                             \
            fma2(qf, wa.y, (VREC)[j], qf);                             \
            fma2(qg, wb.x, (VREC)[j], qg);                             \
            fma2(qo, wb.y, (VREC)[j], qo);                             \
        }                                                              \
        add2(ai, ai, qi); add2(af, af, qf);                            \
        add2(ag, ag, qg); add2(ao, ao, qo);                            \
        CELL_BCAST(ai, af, ag, ao, CA, CB, HA, HB, HP);                \
    }

__global__ void __launch_bounds__(TPB, 1)
lstm2x_kernel(const float* __restrict__ x, float* __restrict__ out, int B)
{
    __shared__ __align__(16) float sw[6 * PK];
    for (int i = threadIdx.x; i < 6 * PK; i += TPB) sw[i] = g_packk[i];
    __syncthreads();

    int wid  = blockIdx.x * WPB + (threadIdx.x >> 5);
    int lane = threadIdx.x & 31;
    if (wid * EPW >= B) return;                     // warp-uniform exit

    int sub = lane / HD;                            // 0..4 active, 5 = spare
    int k   = lane - sub * HD;
    int sb  = (sub < 5) ? sub * HD : 0;             // shuffle base
    int subv = (sub < 5) ? sub : 0;

    int ea = wid * EPW + 2 * subv;                  // element A
    int eb = ea + 1;                                // element B
    bool oka = (sub < 5) && (ea < B) && (k == 0);
    bool okb = (sub < 5) && (eb < B) && (k == 0);
    int la = (ea < B) ? ea : (B - 1);               // clamped for loads
    int lb = (eb < B) ? eb : (B - 1);

    const float* pk = sw + k * PK;
    const ull* s8 = reinterpret_cast<const ull*>(pk);

    // hoist biases + layer-0 x-weights ONLY (regs ~160; no matrix hoisting)
    ull b0i = s8[0],  b0f = s8[1],  b0g = s8[2],  b0o = s8[3];
    ull wxi = s8[4],  wxf = s8[5],  wxg = s8[6],  wxo = s8[7];
    ull b1i = s8[32], b1f = s8[33], b1g = s8[34], b1o = s8[35];
    ull b2i = s8[84], b2f = s8[85], b2g = s8[86], b2o = s8[87];
    float fcwk = pk[288], fcbv = pk[289];

    const ulonglong2* w0c   = reinterpret_cast<const ulonglong2*>(s8 + 8);   // Whh0
    const ulonglong2* w1in  = reinterpret_cast<const ulonglong2*>(s8 + 36);  // Wih1
    const ulonglong2* w1rec = reinterpret_cast<const ulonglong2*>(s8 + 60);  // Whh1
    const ulonglong2* w2in  = reinterpret_cast<const ulonglong2*>(s8 + 88);  // Wih2
    const ulonglong2* w2rec = reinterpret_cast<const ulonglong2*>(s8 + 112); // Whh2

    const float4* xpa = reinterpret_cast<const float4*>(x + (size_t)la * TT);
    const float4* xpb = reinterpret_cast<const float4*>(x + (size_t)lb * TT);

    // state: broadcast vectors packed (vA, vB); cells scalar per element
    ull h0p[HD], h1p[HD], h2p[HD];
    float c0a = 0.f, c0b = 0.f, c1a = 0.f, c1b = 0.f, c2a = 0.f, c2b = 0.f;
    float h2a = 0.f, h2b = 0.f;
    ull z = pack2(0.f, 0.f);
#pragma unroll
    for (int j = 0; j < HD; j++) { h0p[j] = z; h1p[j] = z; h2p[j] = z; }

#pragma unroll 1
    for (int t4 = 0; t4 < TT / 4; t4++) {
        float4 xqa = __ldg(xpa + t4);
        float4 xqb = __ldg(xpb + t4);
#pragma unroll
        for (int u = 0; u < 4; u++) {
            float xta = (u == 0) ? xqa.x : (u == 1) ? xqa.y : (u == 2) ? xqa.z : xqa.w;
            float xtb = (u == 0) ? xqb.x : (u == 1) ? xqb.y : (u == 2) ? xqb.z : xqb.w;
            ull xx = pack2(xta, xtb);

            // ---- layer 0: b0 + wx*x + Whh0 @ h0p (2 chains) ----
            {
                ull ai, af, ag, ao, qi, qf, qg, qo;
                fma2(ai, wxi, xx, b0i);
                fma2(af, wxf, xx, b0f);
                fma2(ag, wxg, xx, b0g);
                fma2(ao, wxo, xx, b0o);
#pragma unroll
                for (int j = 0; j < 3; j++) {
                    ulonglong2 wa = w0c[2*j], wb = w0c[2*j+1];
                    fma2(ai, wa.x, h0p[j], ai);
                    fma2(af, wa.y, h0p[j], af);
                    fma2(ag, wb.x, h0p[j], ag);
                    fma2(ao, wb.y, h0p[j], ao);
                }
                {   ulonglong2 wa = w0c[6], wb = w0c[7];
                    mul2(qi, wa.x, h0p[3]);
                    mul2(qf, wa.y, h0p[3]);
                    mul2(qg, wb.x, h0p[3]);
                    mul2(qo, wb.y, h0p[3]); }
#pragma unroll
                for (int j = 4; j < HD; j++) {
                    ulonglong2 wa = w0c[2*j], wb = w0c[2*j+1];
                    fma2(qi, wa.x, h0p[j], qi);
                    fma2(qf, wa.y, h0p[j], qf);
                    fma2(qg, wb.x, h0p[j], qg);
                    fma2(qo, wb.y, h0p[j], qo);
                }
                add2(ai, ai, qi); add2(af, af, qf);
                add2(ag, ag, qg); add2(ao, ao, qo);
                float h0na, h0nb;
                CELL_BCAST(ai, af, ag, ao, c0a, c0b, h0na, h0nb, h0p);
            }

            // ---- layer 1 ----
            {
                float h1na, h1nb;
                LAYER(w1in, h0p, w1rec, h1p, b1i, b1f, b1g, b1o,
                      c1a, c1b, h1na, h1nb, h1p);
            }

            // ---- layer 2 ----
            LAYER(w2in, h1p, w2rec, h2p, b2i, b2f, b2g, b2o,
                  c2a, c2b, h2a, h2b, h2p);
        }
    }

    // FC head per element: out[e] = sum_k h2[k]*fc_w[k] + fc_b
    float ra = h2a * fcwk;
    float rb = h2b * fcwk;
    float sa = fcbv, sbv = fcbv;
#pragma unroll
    for (int j = 0; j < HD; j++) {
        sa  += __shfl_sync(0xffffffffu, ra, sb + j);
        sbv += __shfl_sync(0xffffffffu, rb, sb + j);
    }
    if (oka) out[ea] = sa;
    if (okb) out[eb] = sbv;
}

extern "C" void kernel_launch(void* const* d_in, const int* in_sizes, int n_in,
                              void* d_out, int out_size)
{
    const float* x = (const float*)d_in[0];
    int B = in_sizes[0] / TT;                  // 8192
    int warps  = (B + EPW - 1) / EPW;          // 820
    int blocks = (warps + WPB - 1) / WPB;      // 137

    prep_kernel<<<1, 64>>>(
        (const float*)d_in[1],  (const float*)d_in[2],
        (const float*)d_in[3],  (const float*)d_in[4],
        (const float*)d_in[5],  (const float*)d_in[6],
        (const float*)d_in[7],  (const float*)d_in[8],
        (const float*)d_in[9],  (const float*)d_in[10],
        (const float*)d_in[11], (const float*)d_in[12],
        (const float*)d_in[13], (const float*)d_in[14]);

    lstm2x_kernel<<<blocks, TPB>>>(x, (float*)d_out, B);
}

// round 10
// speedup vs baseline: 1.8381x; 1.8381x over previous
#include <cuda_runtime.h>

// LSTMNet: 3-layer LSTM (H=6, input=1), B=8192, T=512, FC head on final h2.
// Round 10: R5 geometry (6-lane split, 5 elem/warp, 12 warps/block, 137 blocks,
// single wave) + COLUMN-PACKED f32x2: accumulators pack (even-j, odd-j) partial
// sums per gate, multiplicands are (h_{2m}, h_{2m+1}) pairs -> no (v,v)
// duplication MOVs (the dominant ALU tax in R5). One horizontal FADD per gate.

#define HD 6
#define TT 512
#define PK 164                 // floats per lane-k slice; 656B stride, conflict-free
#define WPB 12
#define TPB (WPB * 32)
__device__ float g_packk[6 * PK];

// per-k slice layout (floats; prescaled: sigmoid rows * -log2e, tanh row * -2log2e)
//   0: b0[4] scalar (i,f,g,o)      4: wx0[4] scalar
//   8: Whh0 col-pairs: (m*4+g)*2 -> (w[g][2m], w[g][2m+1]), m=0..2  [8..32)
//  32: b1 packed (b,0) x4 [32..40)
//  40: Wih1 col-pairs [40..64)     64: Whh1 col-pairs [64..88)
//  88: b2 packed (b,0) x4 [88..96)
//  96: Wih2 col-pairs [96..120)   120: Whh2 col-pairs [120..144)
// 144: fc_w[k]  145: fc_b

__global__ void prep_kernel(
    const float* __restrict__ Wih0, const float* __restrict__ Whh0,
    const float* __restrict__ bih0, const float* __restrict__ bhh0,
    const float* __restrict__ Wih1, const float* __restrict__ Whh1,
    const float* __restrict__ b_ih1, const float* __restrict__ b_hh1,
    const float* __restrict__ Wih2, const float* __restrict__ Whh2,
    const float* __restrict__ b_ih2, const float* __restrict__ b_hh2,
    const float* __restrict__ fcw, const float* __restrict__ fcb)
{
    int tid = threadIdx.x;
    if (tid < 24) {
        int k = tid / 4, g = tid % 4;
        float s = (g == 2) ? -2.88539008177793f : -1.44269504088896f;
        int row = g * HD + k;             // PyTorch gate order i,f,g,o
        float* p = g_packk + k * PK;
        p[0 + g] = (bih0[row] + bhh0[row]) * s;
        p[4 + g] = Wih0[row] * s;         // input dim = 1
        p[32 + 2 * g] = (b_ih1[row] + b_hh1[row]) * s;  p[33 + 2 * g] = 0.f;
        p[88 + 2 * g] = (b_ih2[row] + b_hh2[row]) * s;  p[89 + 2 * g] = 0.f;
        for (int m = 0; m < 3; m++) {
            int o = (m * 4 + g) * 2;
            p[8   + o] = Whh0[row * HD + 2*m] * s;  p[8   + o + 1] = Whh0[row * HD + 2*m+1] * s;
            p[40  + o] = Wih1[row * HD + 2*m] * s;  p[40  + o + 1] = Wih1[row * HD + 2*m+1] * s;
            p[64  + o] = Whh1[row * HD + 2*m] * s;  p[64  + o + 1] = Whh1[row * HD + 2*m+1] * s;
            p[96  + o] = Wih2[row * HD + 2*m] * s;  p[96  + o + 1] = Wih2[row * HD + 2*m+1] * s;
            p[120 + o] = Whh2[row * HD + 2*m] * s;  p[120 + o + 1] = Whh2[row * HD + 2*m+1] * s;
        }
    }
    if (tid < 6) {
        g_packk[tid * PK + 144] = fcw[tid];
        g_packk[tid * PK + 145] = fcb[0];
    }
}

typedef unsigned long long ull;

// ---- f32x2 + fast-math primitives ----
__device__ __forceinline__ void fma2(ull& d, ull a, ull b, ull c) {
    asm("fma.rn.f32x2 %0, %1, %2, %3;" : "=l"(d) : "l"(a), "l"(b), "l"(c));
}
__device__ __forceinline__ void mul2(ull& d, ull a, ull b) {
    asm("mul.rn.f32x2 %0, %1, %2;" : "=l"(d) : "l"(a), "l"(b));
}
__device__ __forceinline__ ull pack2(float x, float y) {
    ull d; asm("mov.b64 %0, {%1, %2};" : "=l"(d) : "f"(x), "f"(y)); return d;
}
__device__ __forceinline__ float hadd2(ull v) {        // lo + hi
    float x, y; asm("mov.b64 {%0, %1}, %2;" : "=f"(x), "=f"(y) : "l"(v));
    return x + y;
}
__device__ __forceinline__ float ex2_ap(float x) {
    float y; asm("ex2.approx.f32 %0, %1;" : "=f"(y) : "f"(x)); return y;
}
__device__ __forceinline__ float rcp_ap(float x) {
    float y; asm("rcp.approx.f32 %0, %1;" : "=f"(y) : "f"(x)); return y;
}

// prescaled gate pre-activations (paired-rcp): ai,af,ao = -z*log2e; ag = -2z*log2e
__device__ __forceinline__ void cell_s(float ai, float af, float ag, float ao,
                                       float& c, float& h)
{
    float ei = ex2_ap(ai), ef = ex2_ap(af), eg = ex2_ap(ag), eo = ex2_ap(ao);
    float a1 = 1.f + ei, a2 = 1.f + ef, a3 = 1.f + eg, a4 = 1.f + eo;
    float r1 = rcp_ap(a1 * a2);
    float r2 = rcp_ap(a3 * a4);
    float si = r1 * a2;
    float sf = r1 * a1;
    float so = r2 * a3;
    float tg = fmaf(r2 * a4, 2.f, -1.f);
    c = fmaf(sf, c, si * tg);
    float ec = ex2_ap(c * -2.88539008177793f);
    float th = fmaf(rcp_ap(1.f + ec), 2.f, -1.f);
    h = so * th;
}

// broadcast hn across subgroup into 3 column-pairs (h0,h1),(h2,h3),(h4,h5)
#define BCAST3(HN, HP)                                                  \
    {   float v0_ = __shfl_sync(0xffffffffu, (HN), sb + 0);             \
        float v1_ = __shfl_sync(0xffffffffu, (HN), sb + 1);             \
        float v2_ = __shfl_sync(0xffffffffu, (HN), sb + 2);             \
        float v3_ = __shfl_sync(0xffffffffu, (HN), sb + 3);             \
        float v4_ = __shfl_sync(0xffffffffu, (HN), sb + 4);             \
        float v5_ = __shfl_sync(0xffffffffu, (HN), sb + 5);             \
        (HP)[0] = pack2(v0_, v1_);                                      \
        (HP)[1] = pack2(v2_, v3_);                                      \
        (HP)[2] = pack2(v4_, v5_);                                      \
    }

// 12-col layer: acc_g = bias_g(b,0) + sum_m Win[g][m]*vin[m] + Wrec[g][m]*vrec[m]
// WIN/WREC: ulonglong2 arrays, [2m] = gates (i,f), [2m+1] = gates (g,o)
// BIAS: ulonglong2 ptr, [0] = (bi,bf) as two (b,0) ull, [1] = (bg,bo)
#define LAYER12(WIN, VIN, WREC, VREC, BIASP, AI, AF, AG, AO)            \
    {   ull ci_, cf_, cg_, co_;                                         \
        {   ulonglong2 bif_ = (BIASP)[0], bgo_ = (BIASP)[1];            \
            ulonglong2 wa_ = (WIN)[0], wb_ = (WIN)[1];                  \
            fma2(ci_, wa_.x, (VIN)[0], bif_.x);                         \
            fma2(cf_, wa_.y, (VIN)[0], bif_.y);                         \
            fma2(cg_, wb_.x, (VIN)[0], bgo_.x);                         \
            fma2(co_, wb_.y, (VIN)[0], bgo_.y); }                       \
        _Pragma("unroll")                                               \
        for (int m = 1; m < 3; m++) {                                   \
            ulonglong2 wa_ = (WIN)[2*m], wb_ = (WIN)[2*m+1];            \
            fma2(ci_, wa_.x, (VIN)[m], ci_);                            \
            fma2(cf_, wa_.y, (VIN)[m], cf_);                            \
            fma2(cg_, wb_.x, (VIN)[m], cg_);                            \
            fma2(co_, wb_.y, (VIN)[m], co_);                            \
        }                                                               \
        _Pragma("unroll")                                               \
        for (int m = 0; m < 3; m++) {                                   \
            ulonglong2 wa_ = (WREC)[2*m], wb_ = (WREC)[2*m+1];          \
            fma2(ci_, wa_.x, (VREC)[m], ci_);                           \
            fma2(cf_, wa_.y, (VREC)[m], cf_);                           \
            fma2(cg_, wb_.x, (VREC)[m], cg_);                           \
            fma2(co_, wb_.y, (VREC)[m], co_);                           \
        }                                                               \
        AI = hadd2(ci_); AF = hadd2(cf_);                               \
        AG = hadd2(cg_); AO = hadd2(co_);                               \
    }

__global__ void __launch_bounds__(TPB, 1)
lstm6_kernel(const float* __restrict__ x, float* __restrict__ out, int B)
{
    __shared__ __align__(16) float sw[6 * PK];
    for (int i = threadIdx.x; i < 6 * PK; i += TPB) sw[i] = g_packk[i];
    __syncthreads();

    int wid  = blockIdx.x * WPB + (threadIdx.x >> 5);
    int lane = threadIdx.x & 31;
    if (wid * 5 >= B) return;                       // warp-uniform exit

    int sub = lane / HD;                            // 0..4 active, 5 = spare
    int k   = lane - sub * HD;
    int sb  = (sub < 5) ? sub * HD : 0;             // shuffle base
    int elem = wid * 5 + (sub < 5 ? sub : 0);
    bool store_ok = (sub < 5) && (elem < B) && (k == 0);
    if (elem >= B) elem = B - 1;                    // clamp loads only

    const float* pk = sw + k * PK;
    const ull* s8 = reinterpret_cast<const ull*>(pk);

    // hoist small scalars only (regs ~150 target)
    float b0i = pk[0], b0f = pk[1], b0g = pk[2], b0o = pk[3];
    float wxi = pk[4], wxf = pk[5], wxg = pk[6], wxo = pk[7];
    float fcwk = pk[144], fcbv = pk[145];

    const ulonglong2* w0c   = reinterpret_cast<const ulonglong2*>(s8 + 4);   // Whh0 [8..32)
    const ulonglong2* b1p   = reinterpret_cast<const ulonglong2*>(s8 + 16);  // [32..40)
    const ulonglong2* w1in  = reinterpret_cast<const ulonglong2*>(s8 + 20);  // [40..64)
    const ulonglong2* w1rec = reinterpret_cast<const ulonglong2*>(s8 + 32);  // [64..88)
    const ulonglong2* b2p   = reinterpret_cast<const ulonglong2*>(s8 + 44);  // [88..96)
    const ulonglong2* w2in  = reinterpret_cast<const ulonglong2*>(s8 + 48);  // [96..120)
    const ulonglong2* w2rec = reinterpret_cast<const ulonglong2*>(s8 + 60);  // [120..144)

    const float4* xp = reinterpret_cast<const float4*>(x + (size_t)elem * TT);

    // state: 3 column-pairs per layer
    ull h0p[3], h1p[3], h2p[3];
    float c0 = 0.f, c1 = 0.f, c2 = 0.f, h2own = 0.f;
    ull z = pack2(0.f, 0.f);
#pragma unroll
    for (int m = 0; m < 3; m++) { h0p[m] = z; h1p[m] = z; h2p[m] = z; }

#pragma unroll 1
    for (int t4 = 0; t4 < TT / 4; t4++) {
        float4 xq = __ldg(xp + t4);
#pragma unroll
        for (int u = 0; u < 4; u++) {
            float xt = (u == 0) ? xq.x : (u == 1) ? xq.y : (u == 2) ? xq.z : xq.w;

            // ---- layer 0: gates = (b0 + wx*x) + Whh0 @ h0 ----
            {
                float pi = fmaf(wxi, xt, b0i);
                float pf = fmaf(wxf, xt, b0f);
                float pg = fmaf(wxg, xt, b0g);
                float po = fmaf(wxo, xt, b0o);
                ull ci, cf, cg, co;
                {   ulonglong2 wa = w0c[0], wb = w0c[1];
                    mul2(ci, wa.x, h0p[0]);
                    mul2(cf, wa.y, h0p[0]);
                    mul2(cg, wb.x, h0p[0]);
                    mul2(co, wb.y, h0p[0]); }
#pragma unroll
                for (int m = 1; m < 3; m++) {
                    ulonglong2 wa = w0c[2*m], wb = w0c[2*m+1];
                    fma2(ci, wa.x, h0p[m], ci);
                    fma2(cf, wa.y, h0p[m], cf);
                    fma2(cg, wb.x, h0p[m], cg);
                    fma2(co, wb.y, h0p[m], co);
                }
                float ai = pi + hadd2(ci);
                float af = pf + hadd2(cf);
                float ag = pg + hadd2(cg);
                float ao = po + hadd2(co);
                float h0n;
                cell_s(ai, af, ag, ao, c0, h0n);
                BCAST3(h0n, h0p);
            }

            // ---- layer 1 ----
            {
                float ai, af, ag, ao, h1n;
                LAYER12(w1in, h0p, w1rec, h1p, b1p, ai, af, ag, ao);
                cell_s(ai, af, ag, ao, c1, h1n);
                BCAST3(h1n, h1p);
            }

            // ---- layer 2 ----
            {
                float ai, af, ag, ao;
                LAYER12(w2in, h1p, w2rec, h2p, b2p, ai, af, ag, ao);
                cell_s(ai, af, ag, ao, c2, h2own);
                BCAST3(h2own, h2p);
            }
        }
    }

    // FC head: out[e] = sum_k h2[k]*fc_w[k] + fc_b
    float r = h2own * fcwk;
    float s = fcbv;
#pragma unroll
    for (int j = 0; j < HD; j++)
        s += __shfl_sync(0xffffffffu, r, sb + j);
    if (store_ok) out[elem] = s;
}

extern "C" void kernel_launch(void* const* d_in, const int* in_sizes, int n_in,
                              void* d_out, int out_size)
{
    const float* x = (const float*)d_in[0];
    int B = in_sizes[0] / TT;                  // 8192
    int warps  = (B + 4) / 5;                  // 1639
    int blocks = (warps + WPB - 1) / WPB;      // 137

    prep_kernel<<<1, 64>>>(
        (const float*)d_in[1],  (const float*)d_in[2],
        (const float*)d_in[3],  (const float*)d_in[4],
        (const float*)d_in[5],  (const float*)d_in[6],
        (const float*)d_in[7],  (const float*)d_in[8],
        (const float*)d_in[9],  (const float*)d_in[10],
        (const float*)d_in[11], (const float*)d_in[12],
        (const float*)d_in[13], (const float*)d_in[14]);

    lstm6_kernel<<<blocks, TPB>>>(x, (float*)d_out, B);
}

// round 11
// speedup vs baseline: 3.1641x; 1.7214x over previous
#include <cuda_runtime.h>

// LSTMNet: 3-layer LSTM (H=6, input=1), B=8192, T=512, FC head on final h2.
// Round 11: R5 base (champion, 324us: 6-lane split, 5 elem/warp, 12 warps/blk,
// 137 blocks single wave) + tanh.approx.f32 cell:
//   sigma(z) = (1+tanh(z/2))/2 -> sigmoid rows prescaled x0.5, tanh row x1.0;
//   h stored DOUBLED (h~ = 2h = fma(to,th,th)); all h-consuming weights
//   (Whh0, Wih1, Whh1, Wih2, Whh2, fc_w) pre-halved in prep.
//   Cell: 5 MUFU + 5 fma (was 8 MUFU + 12 fma); serial cell path ~45cyc (was ~95).

#define HD 6
#define TT 512
#define PK 164                 // floats per lane-k slice; 656B stride, conflict-free
#define WPB 12
#define TPB (WPB * 32)
__device__ float g_packk[6 * PK];

// per-k slice layout (floats):
//   0: b0[4] (i,f,g,o)   4: wx0[4]   8+4j: Whh0 col j
//  32: b1   36+4j: Wih1 col j   60+4j: Whh1 col j
//  84: b2   88+4j: Wih2 col j  112+4j: Whh2 col j
// 136: fc_w[k] (pre-halved)  137: fc_b
// scales: rows i,f,o: z/2 form -> x0.5 ; row g: x1.0.
// h-consuming weights additionally x0.5 (stored h is 2h).

__global__ void prep_kernel(
    const float* __restrict__ Wih0, const float* __restrict__ Whh0,
    const float* __restrict__ bih0, const float* __restrict__ bhh0,
    const float* __restrict__ Wih1, const float* __restrict__ Whh1,
    const float* __restrict__ bih1, const float* __restrict__ bhh1,
    const float* __restrict__ Wih2, const float* __restrict__ Whh2,
    const float* __restrict__ bih2, const float* __restrict__ bhh2,
    const float* __restrict__ fcw, const float* __restrict__ fcb)
{
    int tid = threadIdx.x;
    if (tid < 24) {
        int k = tid / 4, g = tid % 4;
        float s  = (g == 2) ? 1.0f : 0.5f;    // pre-activation scale
        float sh = s * 0.5f;                  // + compensation for doubled h
        int row = g * HD + k;                 // PyTorch gate order i,f,g,o
        float* p = g_packk + k * PK;
        p[0 + g]  = (bih0[row] + bhh0[row]) * s;
        p[4 + g]  = Wih0[row] * s;            // x input (not doubled)
        p[32 + g] = (bih1[row] + bhh1[row]) * s;
        p[84 + g] = (bih2[row] + bhh2[row]) * s;
        for (int j = 0; j < HD; j++) {
            p[8   + j * 4 + g] = Whh0[row * HD + j] * sh;
            p[36  + j * 4 + g] = Wih1[row * HD + j] * sh;
            p[60  + j * 4 + g] = Whh1[row * HD + j] * sh;
            p[88  + j * 4 + g] = Wih2[row * HD + j] * sh;
            p[112 + j * 4 + g] = Whh2[row * HD + j] * sh;
        }
    }
    if (tid < 6) {
        g_packk[tid * PK + 136] = fcw[tid] * 0.5f;   // consumes doubled h2
        g_packk[tid * PK + 137] = fcb[0];
    }
}

typedef unsigned long long ull;

// ---- f32x2 + fast-math primitives ----
__device__ __forceinline__ void fma2(ull& d, ull a, ull b, ull c) {
    asm("fma.rn.f32x2 %0, %1, %2, %3;" : "=l"(d) : "l"(a), "l"(b), "l"(c));
}
__device__ __forceinline__ void mul2(ull& d, ull a, ull b) {
    asm("mul.rn.f32x2 %0, %1, %2;" : "=l"(d) : "l"(a), "l"(b));
}
__device__ __forceinline__ void add2(ull& d, ull a, ull b) {
    asm("add.rn.f32x2 %0, %1, %2;" : "=l"(d) : "l"(a), "l"(b));
}
__device__ __forceinline__ ull pack2(float x, float y) {
    ull d; asm("mov.b64 %0, {%1, %2};" : "=l"(d) : "f"(x), "f"(y)); return d;
}
__device__ __forceinline__ void unpack2(float& x, float& y, ull v) {
    asm("mov.b64 {%0, %1}, %2;" : "=f"(x), "=f"(y) : "l"(v));
}
__device__ __forceinline__ float tanh_ap(float x) {
    float y; asm("tanh.approx.f32 %0, %1;" : "=f"(y) : "f"(x)); return y;
}

// aif = (zi/2, zf/2), ago = (zg, zo/2)  [h-doubling already folded in weights]
// outputs: c (true cell state), h2x = 2*h (doubled hidden, consumers pre-halved)
__device__ __forceinline__ void cell(ull aif, ull ago, float& c, float& h2x) {
    float ai, af, ag, ao;
    unpack2(ai, af, aif);
    unpack2(ag, ao, ago);
    float ti = tanh_ap(ai);
    float tf = tanh_ap(af);
    float tg = tanh_ap(ag);
    float to = tanh_ap(ao);
    float A  = fmaf(tf, c, c);        // (1+tf)*c   = 2f*c
    float Bv = fmaf(ti, tg, tg);      // (1+ti)*tg  = 2i*g
    c = (A + Bv) * 0.5f;
    float th = tanh_ap(c);
    h2x = fmaf(to, th, th);           // (1+to)*th  = 2*o*tanh(c) = 2h
}

// 12-col matvec (6 input cols + 6 recurrent cols), 2 independent chains.
__device__ __forceinline__ void matvec12(const ulonglong2* __restrict__ w2,
                                         const float vin[HD], const float vrec[HD],
                                         ull bif, ull bgo, ull& aif, ull& ago)
{
    ull a0, a1, b0, b1;
    {   ulonglong2 w = w2[0];
        ull vv = pack2(vin[0], vin[0]);
        fma2(a0, w.x, vv, bif);
        fma2(a1, w.y, vv, bgo); }
#pragma unroll
    for (int j = 1; j < HD; j++) {
        ulonglong2 w = w2[j];
        ull vv = pack2(vin[j], vin[j]);
        fma2(a0, w.x, vv, a0);
        fma2(a1, w.y, vv, a1);
    }
    {   ulonglong2 w = w2[6];
        ull vv = pack2(vrec[0], vrec[0]);
        mul2(b0, w.x, vv);
        mul2(b1, w.y, vv); }
#pragma unroll
    for (int j = 1; j < HD; j++) {
        ulonglong2 w = w2[6 + j];
        ull vv = pack2(vrec[j], vrec[j]);
        fma2(b0, w.x, vv, b0);
        fma2(b1, w.y, vv, b1);
    }
    add2(aif, a0, b0);
    add2(ago, a1, b1);
}

__global__ void __launch_bounds__(TPB, 1)
lstm6_kernel(const float* __restrict__ x, float* __restrict__ out, int B)
{
    __shared__ __align__(16) float sw[6 * PK];
    for (int i = threadIdx.x; i < 6 * PK; i += TPB) sw[i] = g_packk[i];
    __syncthreads();

    int wid  = blockIdx.x * WPB + (threadIdx.x >> 5);
    int lane = threadIdx.x & 31;
    if (wid * 5 >= B) return;                       // warp-uniform exit

    int sub = lane / HD;                            // 0..4 active, 5 = spare
    int k   = lane - sub * HD;
    int sb  = (sub < 5) ? sub * HD : 0;             // shuffle base
    int elem = wid * 5 + (sub < 5 ? sub : 0);
    bool store_ok = (sub < 5) && (elem < B) && (k == 0);
    if (elem >= B) elem = B - 1;                    // clamp loads only

    const float* pk = sw + k * PK;
    const ull* pk8 = reinterpret_cast<const ull*>(pk);

    // hoist biases + layer-0 x-weights + fc only (R5-proven reg budget)
    ull b0if = pk8[0],  b0go = pk8[1];
    ull wxif = pk8[2],  wxgo = pk8[3];
    ull b1if = pk8[16], b1go = pk8[17];
    ull b2if = pk8[42], b2go = pk8[43];
    float fcwk = pk[136], fcbv = pk[137];

    const ulonglong2* w0c = reinterpret_cast<const ulonglong2*>(pk8 + 4);  // 6 cols
    const ulonglong2* w1c = reinterpret_cast<const ulonglong2*>(pk8 + 18); // 12 cols
    const ulonglong2* w2c = reinterpret_cast<const ulonglong2*>(pk8 + 44); // 12 cols

    const float4* xp = reinterpret_cast<const float4*>(x + (size_t)elem * TT);

    float h0v[HD], h1v[HD], h2v[HD];
    float c0 = 0.f, c1 = 0.f, c2 = 0.f, h2own = 0.f;
#pragma unroll
    for (int j = 0; j < HD; j++) h0v[j] = h1v[j] = h2v[j] = 0.f;

#pragma unroll 1
    for (int t4 = 0; t4 < TT / 4; t4++) {
        float4 xq = __ldg(xp + t4);
#pragma unroll
        for (int u = 0; u < 4; u++) {
            float xt = (u == 0) ? xq.x : (u == 1) ? xq.y : (u == 2) ? xq.z : xq.w;

            // ---- layer 0: b0 + wx*x + Whh0 @ h0v (2 chains) ----
            ull xx = pack2(xt, xt);
            ull a0, a1, q0, q1, aif, ago;
            fma2(a0, wxif, xx, b0if);
            fma2(a1, wxgo, xx, b0go);
#pragma unroll
            for (int j = 0; j < 3; j++) {
                ulonglong2 w = w0c[j];
                ull vv = pack2(h0v[j], h0v[j]);
                fma2(a0, w.x, vv, a0);
                fma2(a1, w.y, vv, a1);
            }
            {   ulonglong2 w = w0c[3];
                ull vv = pack2(h0v[3], h0v[3]);
                mul2(q0, w.x, vv);
                mul2(q1, w.y, vv); }
#pragma unroll
            for (int j = 4; j < HD; j++) {
                ulonglong2 w = w0c[j];
                ull vv = pack2(h0v[j], h0v[j]);
                fma2(q0, w.x, vv, q0);
                fma2(q1, w.y, vv, q1);
            }
            add2(aif, a0, q0);
            add2(ago, a1, q1);
            float h0n;
            cell(aif, ago, c0, h0n);
#pragma unroll
            for (int j = 0; j < HD; j++)
                h0v[j] = __shfl_sync(0xffffffffu, h0n, sb + j);

            // ---- layer 1 ----
            float h1n;
            matvec12(w1c, h0v, h1v, b1if, b1go, aif, ago);
            cell(aif, ago, c1, h1n);
#pragma unroll
            for (int j = 0; j < HD; j++)
                h1v[j] = __shfl_sync(0xffffffffu, h1n, sb + j);

            // ---- layer 2 ----
            matvec12(w2c, h1v, h2v, b2if, b2go, aif, ago);
            cell(aif, ago, c2, h2own);
#pragma unroll
            for (int j = 0; j < HD; j++)
                h2v[j] = __shfl_sync(0xffffffffu, h2own, sb + j);
        }
    }

    // FC head: out[e] = sum_k (2h2[k])*(fc_w[k]/2) + fc_b
    float r = h2own * fcwk;
    float s = fcbv;
#pragma unroll
    for (int j = 0; j < HD; j++)
        s += __shfl_sync(0xffffffffu, r, sb + j);
    if (store_ok) out[elem] = s;
}

extern "C" void kernel_launch(void* const* d_in, const int* in_sizes, int n_in,
                              void* d_out, int out_size)
{
    const float* x = (const float*)d_in[0];
    int B = in_sizes[0] / TT;                  // 8192
    int warps  = (B + 4) / 5;                  // 1639
    int blocks = (warps + WPB - 1) / WPB;      // 137

    prep_kernel<<<1, 64>>>(
        (const float*)d_in[1],  (const float*)d_in[2],
        (const float*)d_in[3],  (const float*)d_in[4],
        (const float*)d_in[5],  (const float*)d_in[6],
        (const float*)d_in[7],  (const float*)d_in[8],
        (const float*)d_in[9],  (const float*)d_in[10],
        (const float*)d_in[11], (const float*)d_in[12],
        (const float*)d_in[13], (const float*)d_in[14]);

    lstm6_kernel<<<blocks, TPB>>>(x, (float*)d_out, B);
}